// round 1
// baseline (speedup 1.0000x reference)
#include <cuda_runtime.h>
#include <cuda_bf16.h>
#include <math.h>

// Problem constants (match reference)
#define N_NODES 10000
#define N_EDGES 80000
#define IN_DIM  1024
#define HID     4096
#define OUT_DIM 256

// ---------------------------------------------------------------------------
// Scratch (device globals; no dynamic allocation allowed)
// ---------------------------------------------------------------------------
__device__ float g_agg1[(size_t)N_NODES * IN_DIM];   // 40 MB
__device__ float g_agg2[(size_t)N_NODES * HID];      // 160 MB
__device__ float g_h[(size_t)N_NODES * HID];         // 160 MB
__device__ float g_cnt[N_NODES];

// ---------------------------------------------------------------------------
// Utility kernels
// ---------------------------------------------------------------------------
__global__ void zero_kernel(float* __restrict__ p, size_t n4) {
    // n4 = number of float4 elements
    size_t i = (size_t)blockIdx.x * blockDim.x + threadIdx.x;
    size_t stride = (size_t)gridDim.x * blockDim.x;
    float4 z = make_float4(0.f, 0.f, 0.f, 0.f);
    float4* p4 = (float4*)p;
    for (; i < n4; i += stride) p4[i] = z;
}

__global__ void count_kernel(const int* __restrict__ dst, float* __restrict__ cnt) {
    int e = blockIdx.x * blockDim.x + threadIdx.x;
    if (e < N_EDGES) atomicAdd(&cnt[dst[e]], 1.0f);
}

// one block per edge; D4 = feature dim / 4
__global__ void scatter_kernel(const float* __restrict__ X,
                               const int* __restrict__ src,
                               const int* __restrict__ dst,
                               float* __restrict__ agg, int D4) {
    int e = blockIdx.x;
    int s = src[e], d = dst[e];
    const float4* xs = (const float4*)(X + (size_t)s * D4 * 4);
    float* ag = agg + (size_t)d * D4 * 4;
    for (int i = threadIdx.x; i < D4; i += blockDim.x) {
        float4 v = xs[i];
        atomicAdd(ag + 4 * i + 0, v.x);
        atomicAdd(ag + 4 * i + 1, v.y);
        atomicAdd(ag + 4 * i + 2, v.z);
        atomicAdd(ag + 4 * i + 3, v.w);
    }
}

// divide each row by max(cnt,1); one block per node
__global__ void mean_kernel(float* __restrict__ agg, const float* __restrict__ cnt, int D4) {
    int n = blockIdx.x;
    float inv = 1.0f / fmaxf(cnt[n], 1.0f);
    float4* p = (float4*)(agg + (size_t)n * D4 * 4);
    for (int i = threadIdx.x; i < D4; i += blockDim.x) {
        float4 v = p[i];
        v.x *= inv; v.y *= inv; v.z *= inv; v.w *= inv;
        p[i] = v;
    }
}

// ---------------------------------------------------------------------------
// Tiled fp32 GEMM:  C[M,N] = A[M,K] @ W[N,K]^T  (+bias)(+=C)(relu)
// BM=BN=128, BK=8, 256 threads, 8x8 per thread.
// Requires: N % 128 == 0, K % 8 == 0. M may be arbitrary.
// flags: 1 = add bias, 2 = accumulate into C, 4 = relu
// ---------------------------------------------------------------------------
__global__ __launch_bounds__(256, 2)
void gemm_nt_kernel(const float* __restrict__ A, const float* __restrict__ W,
                    const float* __restrict__ bias, float* __restrict__ C,
                    int M, int N, int K, int flags) {
    __shared__ float As[8][128];
    __shared__ float Bs[8][128];

    const int tid = threadIdx.x;
    const int row0 = blockIdx.y * 128;
    const int col0 = blockIdx.x * 128;

    const int tr = (tid / 16) * 8;   // thread tile row offset within block
    const int tc = (tid % 16) * 8;   // thread tile col offset within block

    const int lr = tid >> 1;         // 0..127 : which row of the tile to load
    const int lk = (tid & 1) * 4;    // 0 or 4 : which half of BK

    float acc[8][8];
#pragma unroll
    for (int i = 0; i < 8; i++)
#pragma unroll
        for (int j = 0; j < 8; j++) acc[i][j] = 0.f;

    const int arow = row0 + lr;
    const bool arow_ok = arow < M;
    const int wrow = col0 + lr;       // always < N (N % 128 == 0)

    for (int k0 = 0; k0 < K; k0 += 8) {
        float4 av = make_float4(0.f, 0.f, 0.f, 0.f);
        if (arow_ok) av = *(const float4*)(A + (size_t)arow * K + k0 + lk);
        As[lk + 0][lr] = av.x; As[lk + 1][lr] = av.y;
        As[lk + 2][lr] = av.z; As[lk + 3][lr] = av.w;

        float4 wv = *(const float4*)(W + (size_t)wrow * K + k0 + lk);
        Bs[lk + 0][lr] = wv.x; Bs[lk + 1][lr] = wv.y;
        Bs[lk + 2][lr] = wv.z; Bs[lk + 3][lr] = wv.w;

        __syncthreads();

#pragma unroll
        for (int kk = 0; kk < 8; kk++) {
            float4 a0 = *(const float4*)&As[kk][tr];
            float4 a1 = *(const float4*)&As[kk][tr + 4];
            float4 b0 = *(const float4*)&Bs[kk][tc];
            float4 b1 = *(const float4*)&Bs[kk][tc + 4];
            float af[8] = {a0.x, a0.y, a0.z, a0.w, a1.x, a1.y, a1.z, a1.w};
            float bf[8] = {b0.x, b0.y, b0.z, b0.w, b1.x, b1.y, b1.z, b1.w};
#pragma unroll
            for (int i = 0; i < 8; i++)
#pragma unroll
                for (int j = 0; j < 8; j++)
                    acc[i][j] = fmaf(af[i], bf[j], acc[i][j]);
        }
        __syncthreads();
    }

    const bool hasBias = flags & 1;
    const bool doAcc   = flags & 2;
    const bool doRelu  = flags & 4;

#pragma unroll
    for (int i = 0; i < 8; i++) {
        int r = row0 + tr + i;
        if (r >= M) break;
        float* crow = C + (size_t)r * N;
#pragma unroll
        for (int j = 0; j < 8; j++) {
            int c = col0 + tc + j;
            float v = acc[i][j];
            if (hasBias) v += bias[c];
            if (doAcc)   v += crow[c];
            if (doRelu)  v = fmaxf(v, 0.f);
            crow[c] = v;
        }
    }
}

// ---------------------------------------------------------------------------
// In-place log_softmax over rows of 256; one block (256 threads) per row.
// ---------------------------------------------------------------------------
__global__ void log_softmax_kernel(float* __restrict__ out) {
    __shared__ float red[256];
    const int n = blockIdx.x;
    const int t = threadIdx.x;
    float* row = out + (size_t)n * OUT_DIM;
    float v = row[t];

    red[t] = v;
    __syncthreads();
    for (int s = 128; s > 0; s >>= 1) {
        if (t < s) red[t] = fmaxf(red[t], red[t + s]);
        __syncthreads();
    }
    float m = red[0];
    __syncthreads();

    red[t] = expf(v - m);
    __syncthreads();
    for (int s = 128; s > 0; s >>= 1) {
        if (t < s) red[t] += red[t + s];
        __syncthreads();
    }
    float lse = logf(red[0]);
    row[t] = v - m - lse;
}

// ---------------------------------------------------------------------------
// Launch
// ---------------------------------------------------------------------------
extern "C" void kernel_launch(void* const* d_in, const int* in_sizes, int n_in,
                              void* d_out, int out_size) {
    const float* x   = (const float*)d_in[0];
    const int*   ei  = (const int*)  d_in[1];
    const float* W1l = (const float*)d_in[2];
    const float* b1l = (const float*)d_in[3];
    const float* W1r = (const float*)d_in[4];
    const float* W2l = (const float*)d_in[5];
    const float* b2l = (const float*)d_in[6];
    const float* W2r = (const float*)d_in[7];
    float* out = (float*)d_out;

    const int* src = ei;
    const int* dst = ei + N_EDGES;

    float *agg1, *agg2, *h, *cnt;
    cudaGetSymbolAddress((void**)&agg1, g_agg1);
    cudaGetSymbolAddress((void**)&agg2, g_agg2);
    cudaGetSymbolAddress((void**)&h,    g_h);
    cudaGetSymbolAddress((void**)&cnt,  g_cnt);

    // ---- layer 1 aggregation ----
    zero_kernel<<<2048, 256>>>(agg1, (size_t)N_NODES * IN_DIM / 4);
    zero_kernel<<<16, 256>>>(cnt, N_NODES / 4);
    count_kernel<<<(N_EDGES + 255) / 256, 256>>>(dst, cnt);
    scatter_kernel<<<N_EDGES, 256>>>(x, src, dst, agg1, IN_DIM / 4);
    mean_kernel<<<N_NODES, 256>>>(agg1, cnt, IN_DIM / 4);

    // ---- layer 1 GEMMs: h = relu(mean@W1l^T + b1 + x@W1r^T) ----
    {
        dim3 grid(HID / 128, (N_NODES + 127) / 128);
        gemm_nt_kernel<<<grid, 256>>>(agg1, W1l, b1l, h, N_NODES, HID, IN_DIM, /*bias*/1);
        gemm_nt_kernel<<<grid, 256>>>(x,    W1r, b1l, h, N_NODES, HID, IN_DIM, /*acc|relu*/2 | 4);
    }

    // ---- layer 2 aggregation ----
    zero_kernel<<<4096, 256>>>(agg2, (size_t)N_NODES * HID / 4);
    scatter_kernel<<<N_EDGES, 256>>>(h, src, dst, agg2, HID / 4);
    mean_kernel<<<N_NODES, 256>>>(agg2, cnt, HID / 4);

    // ---- layer 2 GEMMs: out = mean2@W2l^T + b2 + h@W2r^T ----
    {
        dim3 grid(OUT_DIM / 128, (N_NODES + 127) / 128);
        gemm_nt_kernel<<<grid, 256>>>(agg2, W2l, b2l, out, N_NODES, OUT_DIM, HID, /*bias*/1);
        gemm_nt_kernel<<<grid, 256>>>(h,    W2r, b2l, out, N_NODES, OUT_DIM, HID, /*acc*/2);
    }

    // ---- log_softmax (in place on d_out) ----
    log_softmax_kernel<<<N_NODES, 256>>>(out);
}

// round 2
// speedup vs baseline: 3.7229x; 3.7229x over previous
#include <cuda_runtime.h>
#include <cuda_bf16.h>
#include <math.h>
#include <stdint.h>

// Problem constants
#define N_NODES 10000
#define N_EDGES 80000
#define IN_DIM  1024
#define HID     4096
#define OUT_DIM 256

// ---------------------------------------------------------------------------
// Scratch (device globals; 16B-aligned for vector/cp.async access)
// ---------------------------------------------------------------------------
__device__ __align__(16) float g_agg1[(size_t)N_NODES * IN_DIM];   // 40 MB
__device__ __align__(16) float g_h[(size_t)N_NODES * HID];         // 160 MB
__device__ __align__(16) float g_t2[(size_t)N_NODES * OUT_DIM];    // 10 MB
__device__ __align__(16) float g_aggo[(size_t)N_NODES * OUT_DIM];  // 10 MB
__device__ __align__(16) float g_cnt[N_NODES];

// ---------------------------------------------------------------------------
// Utility kernels
// ---------------------------------------------------------------------------
__global__ void zero_kernel(float* __restrict__ p, size_t n4) {
    size_t i = (size_t)blockIdx.x * blockDim.x + threadIdx.x;
    size_t stride = (size_t)gridDim.x * blockDim.x;
    float4 z = make_float4(0.f, 0.f, 0.f, 0.f);
    float4* p4 = (float4*)p;
    for (; i < n4; i += stride) p4[i] = z;
}

__global__ void count_kernel(const int* __restrict__ dst, float* __restrict__ cnt) {
    int e = blockIdx.x * blockDim.x + threadIdx.x;
    if (e < N_EDGES) atomicAdd(&cnt[dst[e]], 1.0f);
}

// one block per edge; D4 = feature dim / 4; blockDim.x == D4
__global__ void scatter_kernel(const float* __restrict__ X,
                               const int* __restrict__ src,
                               const int* __restrict__ dst,
                               float* __restrict__ agg, int D4) {
    int e = blockIdx.x;
    int s = src[e], d = dst[e];
    const float4* xs = (const float4*)(X + (size_t)s * D4 * 4);
    float* ag = agg + (size_t)d * D4 * 4;
    for (int i = threadIdx.x; i < D4; i += blockDim.x) {
        float4 v = xs[i];
        atomicAdd(ag + 4 * i + 0, v.x);
        atomicAdd(ag + 4 * i + 1, v.y);
        atomicAdd(ag + 4 * i + 2, v.z);
        atomicAdd(ag + 4 * i + 3, v.w);
    }
}

__global__ void mean_kernel(float* __restrict__ agg, const float* __restrict__ cnt, int D4) {
    int n = blockIdx.x;
    float inv = 1.0f / fmaxf(cnt[n], 1.0f);
    float4* p = (float4*)(agg + (size_t)n * D4 * 4);
    for (int i = threadIdx.x; i < D4; i += blockDim.x) {
        float4 v = p[i];
        v.x *= inv; v.y *= inv; v.z *= inv; v.w *= inv;
        p[i] = v;
    }
}

// ---------------------------------------------------------------------------
// TF32 tensor-core GEMM:  C[M,N] = A[M,K] @ W[N,K]^T
// BM=BN=128, BK=16, 256 threads = 8 warps (2m x 4n), warp tile 64x32,
// mma.sync.m16n8k8.tf32, cp.async double-buffered smem.
//
// NPAIRS==2: C0 = act(A0@W0^T + A1@W1^T + bias)           (layer 1 fusion)
// SPLITN   : grid.x doubled: first half -> C0 = A0@W0^T + bias
//                            second half -> C1 = A0@W1^T  (no bias)
// ---------------------------------------------------------------------------
#define BM 128
#define BN 128
#define BK 16
#define SKEW 20   // floats per smem row (16 + 4 pad) -> conflict-free frag LDS

__device__ __forceinline__ uint32_t cvt_tf32(float x) {
    uint32_t u; asm("cvt.rna.tf32.f32 %0, %1;" : "=r"(u) : "f"(x)); return u;
}

__device__ __forceinline__ void mma_tf32(float c[4],
        uint32_t a0, uint32_t a1, uint32_t a2, uint32_t a3,
        uint32_t b0, uint32_t b1) {
    asm volatile(
        "mma.sync.aligned.m16n8k8.row.col.f32.tf32.tf32.f32 "
        "{%0,%1,%2,%3},{%4,%5,%6,%7},{%8,%9},{%0,%1,%2,%3};"
        : "+f"(c[0]), "+f"(c[1]), "+f"(c[2]), "+f"(c[3])
        : "r"(a0), "r"(a1), "r"(a2), "r"(a3), "r"(b0), "r"(b1));
}

__device__ __forceinline__ void cp_async16(uint32_t smem, const void* g, bool valid) {
    int sz = valid ? 16 : 0;
    asm volatile("cp.async.ca.shared.global [%0], [%1], 16, %2;\n"
                 :: "r"(smem), "l"(g), "r"(sz));
}
__device__ __forceinline__ void cp_commit() {
    asm volatile("cp.async.commit_group;\n");
}
template<int W8> __device__ __forceinline__ void cp_wait() {
    asm volatile("cp.async.wait_group %0;\n" :: "n"(W8));
}

__device__ __forceinline__ void load_tile(float (*sA)[SKEW], float (*sB)[SKEW],
        const float* __restrict__ A, const float* __restrict__ W,
        int M, int K, int row0, int col0, int k0, int tid) {
#pragma unroll
    for (int it = 0; it < 2; it++) {
        int i  = tid + it * 256;
        int r  = i >> 2;           // 0..127
        int k4 = (i & 3) * 4;      // 0,4,8,12
        bool okA = (row0 + r) < M;
        int ra = okA ? (row0 + r) : 0;
        uint32_t sa = (uint32_t)__cvta_generic_to_shared(&sA[r][k4]);
        cp_async16(sa, A + (size_t)ra * K + k0 + k4, okA);
        uint32_t sb = (uint32_t)__cvta_generic_to_shared(&sB[r][k4]);
        cp_async16(sb, W + (size_t)(col0 + r) * K + k0 + k4, true);
    }
    cp_commit();
}

template<int NPAIRS, bool SPLITN, bool RELU>
__global__ __launch_bounds__(256, 2)
void gemm_tf32_kernel(const float* __restrict__ A0, const float* __restrict__ W0,
                      const float* __restrict__ A1, const float* __restrict__ W1,
                      float* __restrict__ C0, float* __restrict__ C1,
                      const float* __restrict__ bias,
                      int M, int N, int K) {
    __shared__ float sA[2][BM][SKEW];
    __shared__ float sB[2][BN][SKEW];

    const int tid = threadIdx.x;
    const int bx = blockIdx.x, by = blockIdx.y;

    const float* A = A0;
    const float* W = W0;
    float*       C = C0;
    bool useBias = (bias != nullptr);
    int col0;
    if (SPLITN) {
        int nHalf = N / BN;
        bool sel = bx >= nHalf;
        col0 = (sel ? bx - nHalf : bx) * BN;
        if (sel) { W = W1; C = C1; useBias = false; }
    } else {
        col0 = bx * BN;
    }
    const int row0 = by * BM;

    const int w  = tid >> 5, lane = tid & 31;
    const int wr = w >> 2;          // 0..1 -> m offset wr*64
    const int wc = w & 3;           // 0..3 -> n offset wc*32
    const int g  = lane >> 2;       // 0..7
    const int tg = lane & 3;        // 0..3

    float acc[4][4][4];
#pragma unroll
    for (int mi = 0; mi < 4; mi++)
#pragma unroll
        for (int ni = 0; ni < 4; ni++)
#pragma unroll
            for (int q = 0; q < 4; q++) acc[mi][ni][q] = 0.f;

    const int stepsPerK = K / BK;
    const int nSteps = stepsPerK * NPAIRS;

    // prologue: issue step 0 into buffer 0
    load_tile(sA[0], sB[0], A, W, M, K, row0, col0, 0, tid);

    int buf = 0;
    for (int s = 0; s < nSteps; s++) {
        if (s + 1 < nSteps) {
            int sn = s + 1;
            const float* Ap = A; const float* Wp = W; int k0;
            if (NPAIRS == 2 && sn >= stepsPerK) { Ap = A1; Wp = W1; k0 = (sn - stepsPerK) * BK; }
            else k0 = sn * BK;
            load_tile(sA[buf ^ 1], sB[buf ^ 1], Ap, Wp, M, K, row0, col0, k0, tid);
            cp_wait<1>();
        } else {
            cp_wait<0>();
        }
        __syncthreads();

#pragma unroll
        for (int ks = 0; ks < BK; ks += 8) {
            uint32_t af[4][4], bf[4][2];
#pragma unroll
            for (int mi = 0; mi < 4; mi++) {
                int m = wr * 64 + mi * 16;
                af[mi][0] = cvt_tf32(sA[buf][m + g    ][ks + tg]);
                af[mi][1] = cvt_tf32(sA[buf][m + g + 8][ks + tg]);
                af[mi][2] = cvt_tf32(sA[buf][m + g    ][ks + tg + 4]);
                af[mi][3] = cvt_tf32(sA[buf][m + g + 8][ks + tg + 4]);
            }
#pragma unroll
            for (int ni = 0; ni < 4; ni++) {
                int n = wc * 32 + ni * 8;
                bf[ni][0] = cvt_tf32(sB[buf][n + g][ks + tg]);
                bf[ni][1] = cvt_tf32(sB[buf][n + g][ks + tg + 4]);
            }
#pragma unroll
            for (int mi = 0; mi < 4; mi++)
#pragma unroll
                for (int ni = 0; ni < 4; ni++)
                    mma_tf32(acc[mi][ni], af[mi][0], af[mi][1], af[mi][2], af[mi][3],
                             bf[ni][0], bf[ni][1]);
        }
        __syncthreads();
        buf ^= 1;
    }

    // epilogue
#pragma unroll
    for (int mi = 0; mi < 4; mi++) {
        int rbase = row0 + wr * 64 + mi * 16 + g;
#pragma unroll
        for (int half = 0; half < 2; half++) {
            int r = rbase + half * 8;
            if (r < M) {
                float* crow = C + (size_t)r * N;
#pragma unroll
                for (int ni = 0; ni < 4; ni++) {
                    int c = col0 + wc * 32 + ni * 8 + 2 * tg;
                    float v0 = acc[mi][ni][half * 2 + 0];
                    float v1 = acc[mi][ni][half * 2 + 1];
                    if (useBias) { v0 += bias[c]; v1 += bias[c + 1]; }
                    if (RELU) { v0 = fmaxf(v0, 0.f); v1 = fmaxf(v1, 0.f); }
                    *(float2*)(crow + c) = make_float2(v0, v1);
                }
            }
        }
    }
}

// ---------------------------------------------------------------------------
// Final: out[n] = log_softmax( out[n] + aggo[n] / max(cnt[n],1) )
// one block (256 threads = OUT_DIM) per node
// ---------------------------------------------------------------------------
__global__ void final_kernel(float* __restrict__ out,
                             const float* __restrict__ aggo,
                             const float* __restrict__ cnt) {
    __shared__ float red[256];
    const int n = blockIdx.x;
    const int t = threadIdx.x;
    float inv = 1.0f / fmaxf(cnt[n], 1.0f);
    size_t idx = (size_t)n * OUT_DIM + t;
    float v = out[idx] + aggo[idx] * inv;

    red[t] = v;
    __syncthreads();
    for (int s = 128; s > 0; s >>= 1) {
        if (t < s) red[t] = fmaxf(red[t], red[t + s]);
        __syncthreads();
    }
    float m = red[0];
    __syncthreads();

    red[t] = expf(v - m);
    __syncthreads();
    for (int s = 128; s > 0; s >>= 1) {
        if (t < s) red[t] += red[t + s];
        __syncthreads();
    }
    float lse = logf(red[0]);
    out[idx] = v - m - lse;
}

// ---------------------------------------------------------------------------
// Launch
// ---------------------------------------------------------------------------
extern "C" void kernel_launch(void* const* d_in, const int* in_sizes, int n_in,
                              void* d_out, int out_size) {
    const float* x   = (const float*)d_in[0];
    const int*   ei  = (const int*)  d_in[1];
    const float* W1l = (const float*)d_in[2];
    const float* b1l = (const float*)d_in[3];
    const float* W1r = (const float*)d_in[4];
    const float* W2l = (const float*)d_in[5];
    const float* b2l = (const float*)d_in[6];
    const float* W2r = (const float*)d_in[7];
    float* out = (float*)d_out;

    const int* src = ei;
    const int* dst = ei + N_EDGES;

    float *agg1, *h, *t2, *aggo, *cnt;
    cudaGetSymbolAddress((void**)&agg1, g_agg1);
    cudaGetSymbolAddress((void**)&h,    g_h);
    cudaGetSymbolAddress((void**)&t2,   g_t2);
    cudaGetSymbolAddress((void**)&aggo, g_aggo);
    cudaGetSymbolAddress((void**)&cnt,  g_cnt);

    // ---- counts + layer-1 aggregation (1024-dim) ----
    zero_kernel<<<2048, 256>>>(agg1, (size_t)N_NODES * IN_DIM / 4);
    zero_kernel<<<512, 256>>>(aggo, (size_t)N_NODES * OUT_DIM / 4);
    zero_kernel<<<16, 256>>>(cnt, N_NODES / 4);
    count_kernel<<<(N_EDGES + 255) / 256, 256>>>(dst, cnt);
    scatter_kernel<<<N_EDGES, 256>>>(x, src, dst, agg1, IN_DIM / 4);
    mean_kernel<<<N_NODES, 256>>>(agg1, cnt, IN_DIM / 4);

    // ---- layer 1: h = relu(mean1@W1l^T + x@W1r^T + b1) (fused dual-K GEMM) ----
    {
        dim3 grid(HID / BN, (N_NODES + BM - 1) / BM);
        gemm_tf32_kernel<2, false, true><<<grid, 256>>>(
            agg1, W1l, x, W1r, h, nullptr, b1l, N_NODES, HID, IN_DIM);
    }

    // ---- layer 2: project first, aggregate after (16x less scatter traffic)
    //      out = h@W2r^T + b2 ;  t2 = h@W2l^T   (fused split-N GEMM) ----
    {
        dim3 grid(2 * OUT_DIM / BN, (N_NODES + BM - 1) / BM);
        gemm_tf32_kernel<1, true, false><<<grid, 256>>>(
            h, W2r, nullptr, W2l, out, t2, b2l, N_NODES, OUT_DIM, HID);
    }

    // ---- scatter-mean of t2 in 256-dim space ----
    scatter_kernel<<<N_EDGES, 64>>>(t2, src, dst, aggo, OUT_DIM / 4);

    // ---- out = log_softmax(out + aggo/cnt) ----
    final_kernel<<<N_NODES, 256>>>(out, aggo, cnt);
}